// round 9
// baseline (speedup 1.0000x reference)
#include <cuda_runtime.h>
#include <cstdint>
#include <math.h>
#include <math_constants.h>

typedef unsigned int u32;

#define E_  64
#define A_  8
#define L_  2048
#define D_  128
#define H_  8
#define DK_ 16

#define NB_     (E_ * A_)      // 512 (e,a) pairs
#define NCHUNK  4
#define CHUNK   (L_ / NCHUNK)  // 512 rows per chunk

#define NSTAGE  3
#define SROWS   24             // rows per stage (3 per warp)
#define STG_F4  (SROWS * 32)   // float4 per stage

// ---------------------------------------------------------------------------
// Device scratch (no cudaMalloc allowed)
// ---------------------------------------------------------------------------
__device__ float  g_P[NB_ * NCHUNK * H_ * D_];   // unnormalized partial acc
__device__ float2 g_S[NB_ * NCHUNK * H_];        // (m, Z) per partial

// ---------------------------------------------------------------------------
__device__ __forceinline__ void cp_async16(u32 dst, const void* src, int sz) {
    asm volatile("cp.async.cg.shared.global [%0], [%1], 16, %2;\n"
                 :: "r"(dst), "l"(src), "r"(sz) : "memory");
}
#define CP_COMMIT() asm volatile("cp.async.commit_group;\n" ::: "memory")
#define CP_WAIT2()  asm volatile("cp.async.wait_group 2;\n" ::: "memory")
#define CP_WAIT0()  asm volatile("cp.async.wait_group 0;\n" ::: "memory")

// ---------------------------------------------------------------------------
// fold8: per-lane partials p[0..7] (4 dims each) -> full 128-dot for head
// (lane & 7), replicated on all 4 lane-groups.
// ---------------------------------------------------------------------------
__device__ __forceinline__ float fold8(const float p[8], int lane) {
    const unsigned FULL = 0xffffffffu;
    int b0 = lane & 1, b1 = (lane >> 1) & 1, b2 = (lane >> 2) & 1;
    float q[4];
#pragma unroll
    for (int i = 0; i < 4; i++) {
        float t = b0 ? p[2 * i] : p[2 * i + 1];
        float r = __shfl_xor_sync(FULL, t, 1);
        q[i] = (b0 ? p[2 * i + 1] : p[2 * i]) + r;
    }
    float q2[2];
#pragma unroll
    for (int j = 0; j < 2; j++) {
        float t = b1 ? q[2 * j] : q[2 * j + 1];
        float r = __shfl_xor_sync(FULL, t, 2);
        q2[j] = (b1 ? q[2 * j + 1] : q[2 * j]) + r;
    }
    float t = b2 ? q2[0] : q2[1];
    float r = __shfl_xor_sync(FULL, t, 4);
    float s = (b2 ? q2[1] : q2[0]) + r;
    s += __shfl_xor_sync(FULL, s, 8);
    s += __shfl_xor_sync(FULL, s, 16);
    return s;
}

// ---------------------------------------------------------------------------
// attn kernel: 2048 CTAs; CTA = (b, chunk). Computes folded query u inline
// (overlapped with prologue cp.asyncs), then register-resident flash attn.
// ---------------------------------------------------------------------------
__global__ void __launch_bounds__(256, 2)
attn_kernel(const float* __restrict__ emb, const int* __restrict__ lens,
            const float* __restrict__ gc,  const float* __restrict__ de,
            const float* __restrict__ tb,  const float* __restrict__ load,
            const float* __restrict__ Wq_proj, const float* __restrict__ Wk_proj,
            const float* __restrict__ Wq,      const float* __restrict__ Wk) {
    const unsigned FULL = 0xffffffffu;
    int b    = blockIdx.x >> 2;
    int c    = blockIdx.x & 3;
    int e    = b / A_;
    int a    = b % A_;
    int tid  = threadIdx.x;
    int w    = tid >> 5;
    int lane = tid & 31;

    __shared__ __align__(16) char  smraw[NSTAGE * STG_F4 * 16];  // 36864 B
    __shared__ float su[H_ * D_];                                // 4096 B
    __shared__ float sm_tmp[1920];                               // 7680 B
    float4* stage = (float4*)smraw;

    int len  = lens[b];
    len = max(1, min(L_, len));
    int c0   = c * CHUNK;
    int cend = min(len, c0 + CHUNK);
    int nrows = max(0, cend - c0);
    int total = (nrows + SROWS - 1) / SROWS;

    const float4* src = (const float4*)(emb + (size_t)b * L_ * D_);

    u32 smbase = (u32)__cvta_generic_to_shared(smraw);
    u32 my_off[3];
#pragma unroll
    for (int i = 0; i < 3; i++)
        my_off[i] = (u32)(((3 * w + i) * 32 + lane) * 16);

    // ---- prologue: issue stages 0..2 FIRST (overlap with u-compute) ----
#pragma unroll
    for (int s = 0; s < NSTAGE; s++) {
        if (s < total) {
            int rbase = c0 + s * SROWS + 3 * w;
#pragma unroll
            for (int i = 0; i < 3; i++) {
                int gr = rbase + i;
                int ok = gr < cend;
                const void* sp = src + ((size_t)(ok ? gr : c0) * 32 + lane);
                cp_async16(smbase + (u32)(s * STG_F4 * 16) + my_off[i], sp, ok ? 16 : 0);
            }
        }
        CP_COMMIT();
    }

    // ---- compute folded query u[h][d] into su (overlaps DRAM loads) ----
    {
        float* part = sm_tmp;            // [384..640) actually below:
        float* sx   = sm_tmp;            // [0..384)   context vector
        float* prt  = sm_tmp + 384;      // [384..640) partials (256)
        float* q_s  = sm_tmp + 640;      // [640..768) q (128)
        float* qh_s = sm_tmp + 768;      // [768..896) qh (128)
        float* t_s  = sm_tmp + 896;      // [896..1920) t (1024)
        (void)part;

        for (int i = tid; i < 384; i += 256) {
            float v;
            if (i < 128)      v = gc[e * D_ + i];
            else if (i < 256) v = de[e * D_ + (i - 128)];
            else              v = tb[e * D_ + (i - 256)];
            sx[i] = v;
        }
        __syncthreads();

        // q[o] = sum_i sx[i]*Wq_proj[i,o] + load*W[384,o] + a*W[385,o]
        {
            int o = tid & 127, half = tid >> 7;
            int i0 = half * 192, i1 = i0 + 192;
            float s = 0.f;
            for (int i = i0; i < i1; i++)
                s = fmaf(sx[i], Wq_proj[i * D_ + o], s);
            if (half == 1) {
                s = fmaf(load[b],  Wq_proj[384 * D_ + o], s);
                s = fmaf((float)a, Wq_proj[385 * D_ + o], s);
            }
            prt[tid] = s;
        }
        __syncthreads();
        if (tid < 128) q_s[tid] = prt[tid] + prt[tid + 128];
        __syncthreads();

        // qh[h*16+k] = sum_o q[o]*Wq[h*2048 + o*16 + k]
        {
            int out = tid & 127, half = tid >> 7;
            int h = out >> 4, k = out & 15;
            int o0 = half * 64;
            const float* wq = Wq + h * (D_ * DK_) + k;
            float s = 0.f;
#pragma unroll 4
            for (int o = o0; o < o0 + 64; o++)
                s = fmaf(q_s[o], wq[o * DK_], s);
            prt[tid] = s;
        }
        __syncthreads();
        if (tid < 128) qh_s[tid] = prt[tid] + prt[tid + 128];
        __syncthreads();

        // t[h*128+j] = sum_k qh[h*16+k]*Wk[h*2048 + j*16 + k]
        for (int p = 0; p < 4; p++) {
            int idx = tid + p * 256;
            int h = idx >> 7, j = idx & 127;
            const float* wk = Wk + h * (D_ * DK_) + j * DK_;
            const float* qh = qh_s + h * DK_;
            float s = 0.f;
#pragma unroll
            for (int k = 0; k < DK_; k++) s = fmaf(wk[k], qh[k], s);
            t_s[idx] = s;
        }
        __syncthreads();

        // su[h*128+d] = 0.25 * sum_j Wk_proj[d*128+j] * t[h*128+j]
        {
            float s0 = 0.f, s1 = 0.f, s2 = 0.f, s3 = 0.f;
            int h0 = tid >> 7, d0 = tid & 127;      // idx p*256 + tid
            const float* wp0 = Wk_proj + d0 * D_;
            const float* tp0 = t_s + h0 * D_;
            const float* tp1 = t_s + (h0 + 2) * D_;
            const float* tp2 = t_s + (h0 + 4) * D_;
            const float* tp3 = t_s + (h0 + 6) * D_;
#pragma unroll 4
            for (int j = 0; j < D_; j++) {
                float wv = wp0[j];
                s0 = fmaf(wv, tp0[j], s0);
                s1 = fmaf(wv, tp1[j], s1);
                s2 = fmaf(wv, tp2[j], s2);
                s3 = fmaf(wv, tp3[j], s3);
            }
            su[(h0 + 0) * D_ + d0] = 0.25f * s0;
            su[(h0 + 2) * D_ + d0] = 0.25f * s1;
            su[(h0 + 4) * D_ + d0] = 0.25f * s2;
            su[(h0 + 6) * D_ + d0] = 0.25f * s3;
        }
        __syncthreads();
    }

    // per-lane u for all 8 heads at dims 4*lane..4*lane+3
    float4 u[H_];
#pragma unroll
    for (int h = 0; h < H_; h++)
        u[h] = *(const float4*)(su + h * D_ + 4 * lane);

    float4 acc[H_];
#pragma unroll
    for (int h = 0; h < H_; h++) acc[h] = make_float4(0.f, 0.f, 0.f, 0.f);
    float m = -CUDART_INF_F, Z = 0.f;
    int g = lane >> 3;                       // replica group = row within batch

    int buf = 0;
    for (int s = 0; s < total; s++) {
        CP_WAIT2();                          // this thread's stage-s copies done
        const float4* st = stage + buf * STG_F4;
        int lr = 3 * w;
        float4 e0 = st[(lr + 0) * 32 + lane];
        float4 e1 = st[(lr + 1) * 32 + lane];
        float4 e2 = st[(lr + 2) * 32 + lane];

        // scores (consume e before reissuing into this buffer)
        float s0, s1, s2;
        {
            float pa[8];
#pragma unroll
            for (int h = 0; h < H_; h++) {
                float t = e0.x * u[h].x;
                t = fmaf(e0.y, u[h].y, t);
                t = fmaf(e0.z, u[h].z, t);
                pa[h] = fmaf(e0.w, u[h].w, t);
            }
            s0 = fold8(pa, lane);
#pragma unroll
            for (int h = 0; h < H_; h++) {
                float t = e1.x * u[h].x;
                t = fmaf(e1.y, u[h].y, t);
                t = fmaf(e1.z, u[h].z, t);
                pa[h] = fmaf(e1.w, u[h].w, t);
            }
            s1 = fold8(pa, lane);
#pragma unroll
            for (int h = 0; h < H_; h++) {
                float t = e2.x * u[h].x;
                t = fmaf(e2.y, u[h].y, t);
                t = fmaf(e2.z, u[h].z, t);
                pa[h] = fmaf(e2.w, u[h].w, t);
            }
            s2 = fold8(pa, lane);
        }

        // reissue this buffer for stage s+3 (thread-private: safe, e consumed)
        {
            int sn = s + NSTAGE;
            if (sn < total) {
                int rbase = c0 + sn * SROWS + 3 * w;
#pragma unroll
                for (int i = 0; i < 3; i++) {
                    int gr = rbase + i;
                    int ok = gr < cend;
                    const void* sp = src + ((size_t)(ok ? gr : c0) * 32 + lane);
                    cp_async16(smbase + (u32)(buf * STG_F4 * 16) + my_off[i], sp, ok ? 16 : 0);
                }
            }
            CP_COMMIT();
        }
        if (++buf == NSTAGE) buf = 0;

        // mask invalid rows
        int rbase = c0 + s * SROWS + 3 * w;
        if (rbase + 0 >= cend) s0 = -CUDART_INF_F;
        if (rbase + 1 >= cend) s1 = -CUDART_INF_F;
        if (rbase + 2 >= cend) s2 = -CUDART_INF_F;

        float bm = fmaxf(fmaxf(s0, s1), s2);
        if (__any_sync(FULL, bm > m)) {
            float mn = fmaxf(m, bm);
            float cs = __expf(m - mn);       // exp(-inf)=0 on first hit
            m = mn;
            Z *= cs;
#pragma unroll
            for (int h = 0; h < H_; h++) {
                float ch = __shfl_sync(FULL, cs, h);
                acc[h].x *= ch; acc[h].y *= ch; acc[h].z *= ch; acc[h].w *= ch;
            }
        }

        // exp: group g handles row g (g==3 idle)
        float sg = (g == 0) ? s0 : ((g == 1) ? s1 : s2);
        float pg = (g < 3 && sg > -CUDART_INF_F) ? __expf(sg - m) : 0.f;

        // Z: sum p over rows for head lane&7
        float zs = pg + __shfl_xor_sync(FULL, pg, 8);
        zs += __shfl_xor_sync(FULL, zs, 16);
        Z += zs;

        // accumulate
#pragma unroll
        for (int h = 0; h < H_; h++) {
            float p0 = __shfl_sync(FULL, pg, 0 * 8 + h);
            acc[h].x = fmaf(p0, e0.x, acc[h].x);
            acc[h].y = fmaf(p0, e0.y, acc[h].y);
            acc[h].z = fmaf(p0, e0.z, acc[h].z);
            acc[h].w = fmaf(p0, e0.w, acc[h].w);
        }
#pragma unroll
        for (int h = 0; h < H_; h++) {
            float p1 = __shfl_sync(FULL, pg, 1 * 8 + h);
            acc[h].x = fmaf(p1, e1.x, acc[h].x);
            acc[h].y = fmaf(p1, e1.y, acc[h].y);
            acc[h].z = fmaf(p1, e1.z, acc[h].z);
            acc[h].w = fmaf(p1, e1.w, acc[h].w);
        }
#pragma unroll
        for (int h = 0; h < H_; h++) {
            float p2 = __shfl_sync(FULL, pg, 2 * 8 + h);
            acc[h].x = fmaf(p2, e2.x, acc[h].x);
            acc[h].y = fmaf(p2, e2.y, acc[h].y);
            acc[h].z = fmaf(p2, e2.z, acc[h].z);
            acc[h].w = fmaf(p2, e2.w, acc[h].w);
        }
    }

    // ---- drain pipeline, then CTA reduce (reuses stage smem) ----
    CP_WAIT0();
    __syncthreads();

    float* sm_m  = (float*)smraw;            // [8][8]
    float* sm_Zv = sm_m + 64;                // [8][8]
    float* sm_ac = sm_Zv + 64;               // [8][8][128]

    if (lane < 8) { sm_m[w * 8 + lane] = m; sm_Zv[w * 8 + lane] = Z; }
#pragma unroll
    for (int h = 0; h < H_; h++)
        *(float4*)&sm_ac[((size_t)w * 8 + h) * 128 + 4 * lane] = acc[h];
    __syncthreads();

    size_t base = ((size_t)b * NCHUNK + c) * H_;
#pragma unroll
    for (int it = 0; it < 4; it++) {
        int idx = tid + it * 256;
        int h = idx >> 7, d = idx & 127;
        float M = -CUDART_INF_F;
#pragma unroll
        for (int ww = 0; ww < 8; ww++) M = fmaxf(M, sm_m[ww * 8 + h]);
        float sacc = 0.f;
#pragma unroll
        for (int ww = 0; ww < 8; ww++) {
            float mw = sm_m[ww * 8 + h];
            float ee = (mw == -CUDART_INF_F) ? 0.f : __expf(mw - M);
            sacc = fmaf(ee, sm_ac[((size_t)ww * 8 + h) * 128 + d], sacc);
        }
        g_P[(base + h) * D_ + d] = sacc;
        if (d == 0) {
            float z = 0.f;
#pragma unroll
            for (int ww = 0; ww < 8; ww++) {
                float mw = sm_m[ww * 8 + h];
                float ee = (mw == -CUDART_INF_F) ? 0.f : __expf(mw - M);
                z = fmaf(ee, sm_Zv[ww * 8 + h], z);
            }
            g_S[base + h] = make_float2(M, z);
        }
    }
}

// ---------------------------------------------------------------------------
// Merge: combine 4 chunk-partials, then fused epilogue via
//   pv[h,:] = pooled_ext[h,:] @ Wv_proj ;  ctx[h,k] = pv[h,:]·Wv[h,:,k]
//   out     = ctx @ Wo
// ---------------------------------------------------------------------------
__global__ void __launch_bounds__(256)
merge_kernel(const float* __restrict__ Wv_proj, const float* __restrict__ Wv,
             const float* __restrict__ Wo, float* __restrict__ out) {
    int b   = blockIdx.x;
    int a   = b % A_;
    int tid = threadIdx.x;

    __shared__ float pooled[H_][D_];
    __shared__ float pv[H_][D_];
    __shared__ float ctx[H_ * DK_];
    __shared__ float ec[NCHUNK][H_];
    __shared__ float iZt[H_];

    if (tid < H_) {
        int h = tid;
        float mm[NCHUNK], zz[NCHUNK];
        float M = -CUDART_INF_F;
#pragma unroll
        for (int cc = 0; cc < NCHUNK; cc++) {
            float2 s = g_S[((size_t)b * NCHUNK + cc) * H_ + h];
            mm[cc] = s.x; zz[cc] = s.y;
            M = fmaxf(M, s.x);
        }
        float Zt = 0.f;
#pragma unroll
        for (int cc = 0; cc < NCHUNK; cc++) {
            float e = (mm[cc] == -CUDART_INF_F) ? 0.f : __expf(mm[cc] - M);
            ec[cc][h] = e;
            Zt = fmaf(e, zz[cc], Zt);
        }
        iZt[h] = 1.f / Zt;
    }
    __syncthreads();

    {
        int h = tid >> 5, d4 = tid & 31;    // 256 threads cover [8][32] float4
        const float4* P4 = (const float4*)g_P;
        float4 s = make_float4(0.f, 0.f, 0.f, 0.f);
#pragma unroll
        for (int cc = 0; cc < NCHUNK; cc++) {
            float4 v = P4[(((size_t)b * NCHUNK + cc) * H_ + h) * 32 + d4];
            float e = ec[cc][h];
            s.x = fmaf(e, v.x, s.x);
            s.y = fmaf(e, v.y, s.y);
            s.z = fmaf(e, v.z, s.z);
            s.w = fmaf(e, v.w, s.w);
        }
        float iz = iZt[h];
        s.x *= iz; s.y *= iz; s.z *= iz; s.w *= iz;
        *(float4*)&pooled[h][4 * d4] = s;
    }
    __syncthreads();

    // pv[h][j] = sum_d pooled[h][d]*Wv_proj[d*128+j] + a*Wv_proj[128*128+j]
    {
        int h = tid >> 5, j0 = tid & 31;
        float s0 = 0.f, s1 = 0.f, s2 = 0.f, s3 = 0.f;
        const float* pl = pooled[h];
#pragma unroll 4
        for (int d = 0; d < D_; d++) {
            float p = pl[d];
            const float* wr = Wv_proj + d * D_ + j0;
            s0 = fmaf(p, wr[0],  s0);
            s1 = fmaf(p, wr[32], s1);
            s2 = fmaf(p, wr[64], s2);
            s3 = fmaf(p, wr[96], s3);
        }
        const float* wl = Wv_proj + D_ * D_ + j0;
        float af = (float)a;
        pv[h][j0 +  0] = fmaf(af, wl[0],  s0);
        pv[h][j0 + 32] = fmaf(af, wl[32], s1);
        pv[h][j0 + 64] = fmaf(af, wl[64], s2);
        pv[h][j0 + 96] = fmaf(af, wl[96], s3);
    }
    __syncthreads();

    // ctx[h*16+k] = sum_j pv[h][j] * Wv[(h*128+j)*16+k]
    if (tid < H_ * DK_) {
        int h = tid >> 4, k = tid & 15;
        const float* wv = Wv + h * (D_ * DK_) + k;
        const float* pp = pv[h];
        float s = 0.f;
#pragma unroll 4
        for (int j = 0; j < D_; j++) s = fmaf(pp[j], wv[j * DK_], s);
        ctx[tid] = s;
    }
    __syncthreads();

    if (tid < D_) {
        int o = tid;
        float s = 0.f;
#pragma unroll 8
        for (int i = 0; i < H_ * DK_; i++)
            s = fmaf(ctx[i], Wo[i * D_ + o], s);
        out[(size_t)b * D_ + o] = s;
    }
}

// ---------------------------------------------------------------------------
extern "C" void kernel_launch(void* const* d_in, const int* in_sizes, int n_in,
                              void* d_out, int out_size) {
    const float* gc      = (const float*)d_in[0];
    const float* de      = (const float*)d_in[1];
    const float* tb      = (const float*)d_in[2];
    const float* load    = (const float*)d_in[3];
    const float* emb     = (const float*)d_in[4];
    const int*   lens    = (const int*)  d_in[5];
    const float* Wq_proj = (const float*)d_in[6];
    const float* Wk_proj = (const float*)d_in[7];
    const float* Wv_proj = (const float*)d_in[8];
    const float* Wq      = (const float*)d_in[9];
    const float* Wk      = (const float*)d_in[10];
    const float* Wv      = (const float*)d_in[11];
    const float* Wo      = (const float*)d_in[12];
    float* out = (float*)d_out;

    attn_kernel<<<NB_ * NCHUNK, 256>>>(emb, lens, gc, de, tb, load,
                                       Wq_proj, Wk_proj, Wq, Wk);
    merge_kernel<<<NB_, 256>>>(Wv_proj, Wv, Wo, out);
}